// round 7
// baseline (speedup 1.0000x reference)
#include <cuda_runtime.h>

#define NB 8
#define NN 256
#define ND 128
#define NH 256
#define NK 128

typedef unsigned long long u64t;

// ---------------- scratch ----------------------------------------------------
__device__ float g_hi[NB*NN*NH];      // hi + b1 folded in   (2 MB)
__device__ float g_hj[NB*NN*NH];      // hj                  (2 MB)

// ---------------- packed f32x2 helpers ---------------------------------------
__device__ __forceinline__ u64t add2(u64t a, u64t b) {
    u64t r; asm("add.rn.f32x2 %0, %1, %2;" : "=l"(r) : "l"(a), "l"(b)); return r;
}
__device__ __forceinline__ u64t fma2(u64t a, u64t b, u64t c) {
    u64t r; asm("fma.rn.f32x2 %0, %1, %2, %3;" : "=l"(r) : "l"(a), "l"(b), "l"(c)); return r;
}
__device__ __forceinline__ u64t relu2(u64t a) {
    float lo, hi;
    asm("mov.b64 {%0,%1}, %2;" : "=f"(lo), "=f"(hi) : "l"(a));
    lo = fmaxf(lo, 0.f); hi = fmaxf(hi, 0.f);
    u64t r; asm("mov.b64 %0, {%1,%2};" : "=l"(r) : "f"(lo), "f"(hi)); return r;
}
__device__ __forceinline__ float hsum2(u64t a) {
    float lo, hi;
    asm("mov.b64 {%0,%1}, %2;" : "=f"(lo), "=f"(hi) : "l"(a));
    return lo + hi;
}
__device__ __forceinline__ float ex2a(float v) {
    float y;
    asm("ex2.approx.f32 %0, %1;" : "=f"(y) : "f"(v));
    return y;
}

// ---------------- Kernel A: [2048x128] @ [128x512] with smem-staged W1 -------
__global__ __launch_bounds__(128) void k_embed(const float* __restrict__ ae,
                                               const float* __restrict__ W1,
                                               const float* __restrict__ b1) {
    __shared__ float sa[32][129];
    __shared__ float wseg[64][64];

    int row0  = blockIdx.x * 32;
    int hcol0 = blockIdx.y * 64;
    bool isb  = hcol0 >= 256;
    int gcol  = hcol0 & 255;
    int tid   = threadIdx.x;
    int hq    = tid & 15;
    int rg    = tid >> 4;

    #pragma unroll
    for (int s = 0; s < 8; s++) {
        int idx = s*128 + tid;
        int r = idx >> 5, q = idx & 31;
        float4 v = *(const float4*)&ae[(size_t)(row0 + r)*ND + q*4];
        sa[r][q*4+0] = v.x; sa[r][q*4+1] = v.y;
        sa[r][q*4+2] = v.z; sa[r][q*4+3] = v.w;
    }

    float4 bb = isb ? make_float4(0.f,0.f,0.f,0.f)
                    : *(const float4*)&b1[gcol + hq*4];
    float4 acc0 = bb, acc1 = bb, acc2 = bb, acc3 = bb;

    const float* wbase = W1 + (size_t)(isb ? 128 : 0)*NH + gcol;

    #pragma unroll
    for (int kc = 0; kc < 128; kc += 64) {
        __syncthreads();
        #pragma unroll
        for (int s = 0; s < 8; s++) {
            int idx = s*128 + tid;
            int kk = idx >> 4, q = idx & 15;
            *(float4*)&wseg[kk][q*4] =
                *(const float4*)&wbase[(size_t)(kc + kk)*NH + q*4];
        }
        __syncthreads();

        #pragma unroll 4
        for (int kk = 0; kk < 64; kk++) {
            float4 w = *(const float4*)&wseg[kk][hq*4];
            float a0 = sa[rg*4+0][kc+kk];
            float a1 = sa[rg*4+1][kc+kk];
            float a2 = sa[rg*4+2][kc+kk];
            float a3 = sa[rg*4+3][kc+kk];
            acc0.x = fmaf(a0,w.x,acc0.x); acc0.y = fmaf(a0,w.y,acc0.y);
            acc0.z = fmaf(a0,w.z,acc0.z); acc0.w = fmaf(a0,w.w,acc0.w);
            acc1.x = fmaf(a1,w.x,acc1.x); acc1.y = fmaf(a1,w.y,acc1.y);
            acc1.z = fmaf(a1,w.z,acc1.z); acc1.w = fmaf(a1,w.w,acc1.w);
            acc2.x = fmaf(a2,w.x,acc2.x); acc2.y = fmaf(a2,w.y,acc2.y);
            acc2.z = fmaf(a2,w.z,acc2.z); acc2.w = fmaf(a2,w.w,acc2.w);
            acc3.x = fmaf(a3,w.x,acc3.x); acc3.y = fmaf(a3,w.y,acc3.y);
            acc3.z = fmaf(a3,w.z,acc3.z); acc3.w = fmaf(a3,w.w,acc3.w);
        }
    }

    float* dst = isb ? g_hj : g_hi;
    int c = (isb ? hcol0 - 256 : hcol0) + hq*4;
    int r0 = row0 + rg*4;
    *(float4*)&dst[(size_t)(r0+0)*NH + c] = acc0;
    *(float4*)&dst[(size_t)(r0+1)*NH + c] = acc1;
    *(float4*)&dst[(size_t)(r0+2)*NH + c] = acc2;
    *(float4*)&dst[(size_t)(r0+3)*NH + c] = acc3;
}

// ---------------- Kernel B: warp-specialized pair-MLP + RBF ------------------
// 512 threads: warps 0-7 = producers (pair MLP on a 32x32 tile, 2x2/thread),
// warps 8-15 = consumers (RBF + store). Block processes 2 j-tiles; consume(t)
// runs concurrently with produce(t+1). Both roles span all 4 SMSPs.
#define TI 32
#define TJQ 32
#define HCH 128
#define PADW 132

// dynamic smem layout (floats)
#define OFF_SHI   0                     // 32*132 = 4224
#define OFF_SHJ   (OFF_SHI + TI*PADW)   // 32*132 = 4224
#define OFF_SW0   (OFF_SHJ + TJQ*PADW)  // 256
#define OFF_SW1   (OFF_SW0 + NH)        // 256
#define OFF_BUF   (OFF_SW1 + NH)        // 2 * 2048
#define SMEM_FLOATS (OFF_BUF + 2*2*TI*TJQ)
#define SMEM_BYTES  (SMEM_FLOATS*4)

#define PSTEP4(A0,A1,C0,C1,W0,W1v) {                                     \
    u64t r00 = relu2(add2((A0), (C0)));                                   \
    u64t r01 = relu2(add2((A0), (C1)));                                   \
    u64t r10 = relu2(add2((A1), (C0)));                                   \
    u64t r11 = relu2(add2((A1), (C1)));                                   \
    acc00a = fma2(r00, (W0), acc00a); acc00b = fma2(r00, (W1v), acc00b);  \
    acc01a = fma2(r01, (W0), acc01a); acc01b = fma2(r01, (W1v), acc01b);  \
    acc10a = fma2(r10, (W0), acc10a); acc10b = fma2(r10, (W1v), acc10b);  \
    acc11a = fma2(r11, (W0), acc11a); acc11b = fma2(r11, (W1v), acc11b); }

__global__ __launch_bounds__(512, 2) void k_fused(
        const float* __restrict__ x,
        const float* __restrict__ W2,
        const float* __restrict__ b2,
        const float* __restrict__ means,
        const float* __restrict__ temps,
        float* __restrict__ out) {
    extern __shared__ float sm[];
    float* shi = sm + OFF_SHI;
    float* shj = sm + OFF_SHJ;
    float* sw0 = sm + OFF_SW0;
    float* sw1 = sm + OFF_SW1;

    int b   = blockIdx.z;
    int i0  = blockIdx.y * TI;
    int j00 = blockIdx.x * (2*TJQ);
    int tid  = threadIdx.x;                // 0..511
    int wid  = tid >> 5;
    int lane = tid & 31;
    bool prod = (wid < 8);
    int rtid = tid & 255;                  // role-local 0..255

    const float* hi_base = g_hi + (size_t)(b*NN + i0)*NH;

    if (prod) {
        // W2 columns to smem (ordered before use by bar.sync 1 inside loop)
        #pragma unroll
        for (int h = rtid; h < NH; h += 256) {
            sw0[h] = W2[2*h];
            sw1[h] = W2[2*h + 1];
        }

        int tjj = rtid & 15;               // j rows tjj, tjj+16
        int tii = rtid >> 4;               // i rows tii, tii+16

        #pragma unroll
        for (int t = 0; t < 2; t++) {
            const float* hj_base = g_hj + (size_t)(b*NN + j00 + t*TJQ)*NH;
            float* bmul  = sm + OFF_BUF + t*2*TI*TJQ;
            float* bbias = bmul + TI*TJQ;

            u64t acc00a=0ull, acc00b=0ull, acc01a=0ull, acc01b=0ull;
            u64t acc10a=0ull, acc10b=0ull, acc11a=0ull, acc11b=0ull;

            #pragma unroll
            for (int ch = 0; ch < 2; ch++) {
                asm volatile("bar.sync 1, 256;" ::: "memory");
                // stage shi 32x128 + shj 32x128 = 2048 float4, 8 per thread
                #pragma unroll
                for (int s5 = 0; s5 < 8; s5++) {
                    int idx = s5*256 + rtid;
                    if (idx < 1024) {
                        int r = idx >> 5, c = idx & 31;
                        *(float4*)&shi[r*PADW + c*4] =
                            *(const float4*)&hi_base[(size_t)r*NH + ch*HCH + c*4];
                    } else {
                        int id2 = idx - 1024;
                        int r = id2 >> 5, c = id2 & 31;
                        *(float4*)&shj[r*PADW + c*4] =
                            *(const float4*)&hj_base[(size_t)r*NH + ch*HCH + c*4];
                    }
                }
                asm volatile("bar.sync 1, 256;" ::: "memory");

                const float* wp0 = sw0 + ch*HCH;
                const float* wp1 = sw1 + ch*HCH;
                #pragma unroll 2
                for (int h4 = 0; h4 < HCH/4; h4++) {
                    ulonglong2 A0 = *(const ulonglong2*)&shi[(tii   )*PADW + h4*4];
                    ulonglong2 A1 = *(const ulonglong2*)&shi[(tii+16)*PADW + h4*4];
                    ulonglong2 C0 = *(const ulonglong2*)&shj[(tjj   )*PADW + h4*4];
                    ulonglong2 C1 = *(const ulonglong2*)&shj[(tjj+16)*PADW + h4*4];
                    ulonglong2 W0 = *(const ulonglong2*)&wp0[h4*4];
                    ulonglong2 W1v= *(const ulonglong2*)&wp1[h4*4];
                    PSTEP4(A0.x, A1.x, C0.x, C1.x, W0.x, W1v.x);
                    PSTEP4(A0.y, A1.y, C0.y, C1.y, W0.y, W1v.y);
                }
            }

            {
                const float s = 0.0625f;   // 1/sqrt(2*128)
                float cb0 = __ldg(&b2[0]) * s;
                float cb1 = __ldg(&b2[1]) * s;
                bmul [(tii   )*TJQ + tjj   ] = fmaf(hsum2(acc00a), s, cb0);
                bbias[(tii   )*TJQ + tjj   ] = fmaf(hsum2(acc00b), s, cb1);
                bmul [(tii   )*TJQ + tjj+16] = fmaf(hsum2(acc01a), s, cb0);
                bbias[(tii   )*TJQ + tjj+16] = fmaf(hsum2(acc01b), s, cb1);
                bmul [(tii+16)*TJQ + tjj   ] = fmaf(hsum2(acc10a), s, cb0);
                bbias[(tii+16)*TJQ + tjj   ] = fmaf(hsum2(acc10b), s, cb1);
                bmul [(tii+16)*TJQ + tjj+16] = fmaf(hsum2(acc11a), s, cb0);
                bbias[(tii+16)*TJQ + tjj+16] = fmaf(hsum2(acc11b), s, cb1);
            }
            __syncthreads();               // handoff: buf t ready
        }
        // producers exit; consumers execute no further __syncthreads
    } else {
        // -------- consumers: RBF + store --------
        const float L2E = 1.4426950408889634f;
        int k0 = lane * 4;
        float4 mm4 = *(const float4*)&means[k0];
        float4 tt4 = *(const float4*)&temps[k0];
        float nA0 = -fabsf(tt4.x)*L2E, nA1 = -fabsf(tt4.y)*L2E;
        float nA2 = -fabsf(tt4.z)*L2E, nA3 = -fabsf(tt4.w)*L2E;
        float pB0 = -2.f*nA0*mm4.x, pB1 = -2.f*nA1*mm4.y;
        float pB2 = -2.f*nA2*mm4.z, pB3 = -2.f*nA3*mm4.w;
        float qC0 = nA0*mm4.x*mm4.x, qC1 = nA1*mm4.y*mm4.y;
        float qC2 = nA2*mm4.z*mm4.z, qC3 = nA3*mm4.w*mm4.w;

        int cw = wid - 8;                  // 0..7: warp owns 128 pairs/tile

        #pragma unroll
        for (int t = 0; t < 2; t++) {
            __syncthreads();               // wait: buf t ready
            int j0 = j00 + t*TJQ;
            const float* bmul  = sm + OFF_BUF + t*2*TI*TJQ;
            const float* bbias = bmul + TI*TJQ;
            const float* xrow  = x + (size_t)(b*NN + i0)*NN + j0;
            size_t obase = ((size_t)(b*NN + i0)*NN + j0) * NK + k0;

            #pragma unroll 4
            for (int pp = 0; pp < 128; pp++) {
                int p = cw*128 + pp;       // 0..1023
                int i_loc = p >> 5, j_loc = p & 31;
                float mv = bmul[p];
                float bv = bbias[p];
                float xv = __ldg(&xrow[(size_t)i_loc*NN + j_loc]);
                float v = fmaf(mv, xv, bv);
                float e0 = ex2a(fmaf(fmaf(nA0, v, pB0), v, qC0));
                float e1 = ex2a(fmaf(fmaf(nA1, v, pB1), v, qC1));
                float e2 = ex2a(fmaf(fmaf(nA2, v, pB2), v, qC2));
                float e3 = ex2a(fmaf(fmaf(nA3, v, pB3), v, qC3));
                __stcs((float4*)(out + obase + ((size_t)i_loc*NN + j_loc)*NK),
                       make_float4(e0, e1, e2, e3));
            }
        }
    }
}

// ---------------- launch ------------------------------------------------------
extern "C" void kernel_launch(void* const* d_in, const int* in_sizes, int n_in,
                              void* d_out, int out_size) {
    const float* x     = (const float*)d_in[0];   // (B,N,N)
    const float* ae    = (const float*)d_in[1];   // (B,N,D)
    const float* W1    = (const float*)d_in[2];   // (2D,H)
    const float* b1    = (const float*)d_in[3];   // (H)
    const float* W2    = (const float*)d_in[4];   // (H,2)
    const float* b2    = (const float*)d_in[5];   // (2)
    const float* means = (const float*)d_in[6];   // (K)
    const float* temps = (const float*)d_in[7];   // (K)
    float* out = (float*)d_out;                   // (B,N,N,K)

    dim3 gA(NB*NN/32, 8);                         // 512 blocks
    k_embed<<<gA, 128>>>(ae, W1, b1);

    cudaFuncSetAttribute(k_fused, cudaFuncAttributeMaxDynamicSharedMemorySize,
                         SMEM_BYTES);
    dim3 gB(NN/(2*TJQ), NN/TI, NB);               // (4, 8, 8) = 256 blocks
    k_fused<<<gB, 512, SMEM_BYTES>>>(x, W2, b2, means, temps, out);
}

// round 8
// speedup vs baseline: 1.0505x; 1.0505x over previous
#include <cuda_runtime.h>

#define NB 8
#define NN 256
#define ND 128
#define NH 256
#define NK 128

typedef unsigned long long u64t;

// ---------------- scratch ----------------------------------------------------
__device__ float g_hi[NB*NN*NH];      // hi + b1 folded in   (2 MB)
__device__ float g_hj[NB*NN*NH];      // hj                  (2 MB)

// ---------------- packed f32x2 helpers ---------------------------------------
__device__ __forceinline__ u64t add2(u64t a, u64t b) {
    u64t r; asm("add.rn.f32x2 %0, %1, %2;" : "=l"(r) : "l"(a), "l"(b)); return r;
}
__device__ __forceinline__ u64t fma2(u64t a, u64t b, u64t c) {
    u64t r; asm("fma.rn.f32x2 %0, %1, %2, %3;" : "=l"(r) : "l"(a), "l"(b), "l"(c)); return r;
}
__device__ __forceinline__ u64t relu2(u64t a) {
    float lo, hi;
    asm("mov.b64 {%0,%1}, %2;" : "=f"(lo), "=f"(hi) : "l"(a));
    lo = fmaxf(lo, 0.f); hi = fmaxf(hi, 0.f);
    u64t r; asm("mov.b64 %0, {%1,%2};" : "=l"(r) : "f"(lo), "f"(hi)); return r;
}
__device__ __forceinline__ float hsum2(u64t a) {
    float lo, hi;
    asm("mov.b64 {%0,%1}, %2;" : "=f"(lo), "=f"(hi) : "l"(a));
    return lo + hi;
}
__device__ __forceinline__ float ex2a(float v) {
    float y;
    asm("ex2.approx.f32 %0, %1;" : "=f"(y) : "f"(v));
    return y;
}

// ---------------- Kernel A: [2048x128] @ [128x512] with smem-staged W1 -------
__global__ __launch_bounds__(128) void k_embed(const float* __restrict__ ae,
                                               const float* __restrict__ W1,
                                               const float* __restrict__ b1) {
    __shared__ float sa[32][129];
    __shared__ float wseg[64][64];

    int row0  = blockIdx.x * 32;
    int hcol0 = blockIdx.y * 64;
    bool isb  = hcol0 >= 256;
    int gcol  = hcol0 & 255;
    int tid   = threadIdx.x;
    int hq    = tid & 15;
    int rg    = tid >> 4;

    #pragma unroll
    for (int s = 0; s < 8; s++) {
        int idx = s*128 + tid;
        int r = idx >> 5, q = idx & 31;
        float4 v = *(const float4*)&ae[(size_t)(row0 + r)*ND + q*4];
        sa[r][q*4+0] = v.x; sa[r][q*4+1] = v.y;
        sa[r][q*4+2] = v.z; sa[r][q*4+3] = v.w;
    }

    float4 bb = isb ? make_float4(0.f,0.f,0.f,0.f)
                    : *(const float4*)&b1[gcol + hq*4];
    float4 acc0 = bb, acc1 = bb, acc2 = bb, acc3 = bb;

    const float* wbase = W1 + (size_t)(isb ? 128 : 0)*NH + gcol;

    #pragma unroll
    for (int kc = 0; kc < 128; kc += 64) {
        __syncthreads();
        #pragma unroll
        for (int s = 0; s < 8; s++) {
            int idx = s*128 + tid;
            int kk = idx >> 4, q = idx & 15;
            *(float4*)&wseg[kk][q*4] =
                *(const float4*)&wbase[(size_t)(kc + kk)*NH + q*4];
        }
        __syncthreads();

        #pragma unroll 4
        for (int kk = 0; kk < 64; kk++) {
            float4 w = *(const float4*)&wseg[kk][hq*4];
            float a0 = sa[rg*4+0][kc+kk];
            float a1 = sa[rg*4+1][kc+kk];
            float a2 = sa[rg*4+2][kc+kk];
            float a3 = sa[rg*4+3][kc+kk];
            acc0.x = fmaf(a0,w.x,acc0.x); acc0.y = fmaf(a0,w.y,acc0.y);
            acc0.z = fmaf(a0,w.z,acc0.z); acc0.w = fmaf(a0,w.w,acc0.w);
            acc1.x = fmaf(a1,w.x,acc1.x); acc1.y = fmaf(a1,w.y,acc1.y);
            acc1.z = fmaf(a1,w.z,acc1.z); acc1.w = fmaf(a1,w.w,acc1.w);
            acc2.x = fmaf(a2,w.x,acc2.x); acc2.y = fmaf(a2,w.y,acc2.y);
            acc2.z = fmaf(a2,w.z,acc2.z); acc2.w = fmaf(a2,w.w,acc2.w);
            acc3.x = fmaf(a3,w.x,acc3.x); acc3.y = fmaf(a3,w.y,acc3.y);
            acc3.z = fmaf(a3,w.z,acc3.z); acc3.w = fmaf(a3,w.w,acc3.w);
        }
    }

    float* dst = isb ? g_hj : g_hi;
    int c = (isb ? hcol0 - 256 : hcol0) + hq*4;
    int r0 = row0 + rg*4;
    *(float4*)&dst[(size_t)(r0+0)*NH + c] = acc0;
    *(float4*)&dst[(size_t)(r0+1)*NH + c] = acc1;
    *(float4*)&dst[(size_t)(r0+2)*NH + c] = acc2;
    *(float4*)&dst[(size_t)(r0+3)*NH + c] = acc3;
}

// ---------------- Kernel B: fused pair-MLP + RBF, 50% occupancy --------------
// 256 threads, 32x32 tile, 2x2 pairs/thread (i: tii,tii+16; j: tjj,tjj+16).
// Warp w owns i rows {2w, 2w+1, 2w+16, 2w+17} x all 32 j = 128 pairs:
// phase-2 handoff is per-warp (syncwarp only), no block barrier after MLP.
#define TI 32
#define TJQ 32
#define HCH 128
#define PADW 132

#define PSTEP4(A0,A1,C0,C1,W0,W1v) {                                     \
    u64t r00 = relu2(add2((A0), (C0)));                                   \
    u64t r01 = relu2(add2((A0), (C1)));                                   \
    u64t r10 = relu2(add2((A1), (C0)));                                   \
    u64t r11 = relu2(add2((A1), (C1)));                                   \
    acc00a = fma2(r00, (W0), acc00a); acc00b = fma2(r00, (W1v), acc00b);  \
    acc01a = fma2(r01, (W0), acc01a); acc01b = fma2(r01, (W1v), acc01b);  \
    acc10a = fma2(r10, (W0), acc10a); acc10b = fma2(r10, (W1v), acc10b);  \
    acc11a = fma2(r11, (W0), acc11a); acc11b = fma2(r11, (W1v), acc11b); }

__global__ __launch_bounds__(256, 4) void k_fused(
        const float* __restrict__ x,
        const float* __restrict__ W2,
        const float* __restrict__ b2,
        const float* __restrict__ means,
        const float* __restrict__ temps,
        float* __restrict__ out) {
    __shared__ float shi[TI*PADW];         // 16.5 KB
    __shared__ float shj[TJQ*PADW];        // 16.5 KB
    __shared__ float sw0[NH];              // 1 KB
    __shared__ float sw1[NH];              // 1 KB
    __shared__ float sx[TI*TJQ];           // 4 KB
    __shared__ float wbuf[8][256];         // 8 KB: per-warp mul(128)+bias(128)

    int b   = blockIdx.z;
    int i0  = blockIdx.y * TI;
    int j0  = blockIdx.x * TJQ;
    int tid  = threadIdx.x;                // 0..255
    int lane = tid & 31;
    int wrp  = tid >> 5;                   // 0..7

    // one-time loads: W2 columns and x tile (ordered by first staging barrier)
    #pragma unroll
    for (int h = tid; h < NH; h += 256) {
        sw0[h] = W2[2*h];
        sw1[h] = W2[2*h + 1];
    }
    {
        int r = tid >> 3;                  // 0..31
        int c = tid & 7;                   // 0..7
        *(float4*)&sx[r*TJQ + c*4] =
            *(const float4*)&x[(size_t)(b*NN + i0 + r)*NN + j0 + c*4];
    }

    const float* hi_base = g_hi + (size_t)(b*NN + i0)*NH;
    const float* hj_base = g_hj + (size_t)(b*NN + j0)*NH;

    int tjj = tid & 15;                    // j rows tjj, tjj+16
    int tii = tid >> 4;                    // i rows tii, tii+16

    u64t acc00a=0ull, acc00b=0ull, acc01a=0ull, acc01b=0ull;
    u64t acc10a=0ull, acc10b=0ull, acc11a=0ull, acc11b=0ull;

    #pragma unroll
    for (int ch = 0; ch < 2; ch++) {
        __syncthreads();
        // stage shi 32x128 + shj 32x128 = 2048 float4, 8 per thread
        #pragma unroll
        for (int s5 = 0; s5 < 8; s5++) {
            int idx = s5*256 + tid;
            if (idx < 1024) {
                int r = idx >> 5, c = idx & 31;
                *(float4*)&shi[r*PADW + c*4] =
                    *(const float4*)&hi_base[(size_t)r*NH + ch*HCH + c*4];
            } else {
                int id2 = idx - 1024;
                int r = id2 >> 5, c = id2 & 31;
                *(float4*)&shj[r*PADW + c*4] =
                    *(const float4*)&hj_base[(size_t)r*NH + ch*HCH + c*4];
            }
        }
        __syncthreads();

        const float* wp0 = sw0 + ch*HCH;
        const float* wp1 = sw1 + ch*HCH;
        #pragma unroll 2
        for (int h4 = 0; h4 < HCH/4; h4++) {
            ulonglong2 A0 = *(const ulonglong2*)&shi[(tii   )*PADW + h4*4];
            ulonglong2 A1 = *(const ulonglong2*)&shi[(tii+16)*PADW + h4*4];
            ulonglong2 C0 = *(const ulonglong2*)&shj[(tjj   )*PADW + h4*4];
            ulonglong2 C1 = *(const ulonglong2*)&shj[(tjj+16)*PADW + h4*4];
            ulonglong2 W0 = *(const ulonglong2*)&wp0[h4*4];
            ulonglong2 W1v= *(const ulonglong2*)&wp1[h4*4];
            PSTEP4(A0.x, A1.x, C0.x, C1.x, W0.x, W1v.x);
            PSTEP4(A0.y, A1.y, C0.y, C1.y, W0.y, W1v.y);
        }
    }

    // ---------- per-warp handoff: mul/bias into this warp's slice ----------
    // warp w owns i-slots: s=0 -> 2w, s=1 -> 2w+1, s=2 -> 2w+16, s=3 -> 2w+17
    // thread (tii = 2w + a, tjj): acc00 -> slot a, acc10 -> slot 2+a
    {
        const float s = 0.0625f;           // 1/sqrt(2*128)
        float cb0 = __ldg(&b2[0]) * s;
        float cb1 = __ldg(&b2[1]) * s;
        int a = tii & 1;                   // tii = 2*wrp + a
        float* wm = wbuf[wrp];             // mul [0..127], bias [128..255]
        wm[(a  )*32 + tjj     ] = fmaf(hsum2(acc00a), s, cb0);
        wm[(a  )*32 + tjj + 16] = fmaf(hsum2(acc01a), s, cb0);
        wm[(2+a)*32 + tjj     ] = fmaf(hsum2(acc10a), s, cb0);
        wm[(2+a)*32 + tjj + 16] = fmaf(hsum2(acc11a), s, cb0);
        wm[128 + (a  )*32 + tjj     ] = fmaf(hsum2(acc00b), s, cb1);
        wm[128 + (a  )*32 + tjj + 16] = fmaf(hsum2(acc01b), s, cb1);
        wm[128 + (2+a)*32 + tjj     ] = fmaf(hsum2(acc10b), s, cb1);
        wm[128 + (2+a)*32 + tjj + 16] = fmaf(hsum2(acc11b), s, cb1);
    }
    __syncwarp();

    // ---------- phase 2 (per warp, no block barrier): RBF + store ----------
    const float L2E = 1.4426950408889634f;
    int k0 = lane * 4;
    float4 mm4 = *(const float4*)&means[k0];
    float4 tt4 = *(const float4*)&temps[k0];
    float nA0 = -fabsf(tt4.x)*L2E, nA1 = -fabsf(tt4.y)*L2E;
    float nA2 = -fabsf(tt4.z)*L2E, nA3 = -fabsf(tt4.w)*L2E;
    float pB0 = -2.f*nA0*mm4.x, pB1 = -2.f*nA1*mm4.y;
    float pB2 = -2.f*nA2*mm4.z, pB3 = -2.f*nA3*mm4.w;
    float qC0 = nA0*mm4.x*mm4.x, qC1 = nA1*mm4.y*mm4.y;
    float qC2 = nA2*mm4.z*mm4.z, qC3 = nA3*mm4.w*mm4.w;

    const float* wm = wbuf[wrp];
    size_t obase = ((size_t)(b*NN + i0)*NN + j0) * NK + k0;

    #pragma unroll 4
    for (int pp = 0; pp < 128; pp++) {
        int s2 = pp >> 5;                  // i-slot 0..3
        int j_loc = pp & 31;
        int i_loc = 2*wrp + (s2 & 1) + (s2 >> 1)*16;
        float mv = wm[pp];
        float bv = wm[128 + pp];
        float xv = sx[i_loc*TJQ + j_loc];
        float v = fmaf(mv, xv, bv);
        float e0 = ex2a(fmaf(fmaf(nA0, v, pB0), v, qC0));
        float e1 = ex2a(fmaf(fmaf(nA1, v, pB1), v, qC1));
        float e2 = ex2a(fmaf(fmaf(nA2, v, pB2), v, qC2));
        float e3 = ex2a(fmaf(fmaf(nA3, v, pB3), v, qC3));
        __stcs((float4*)(out + obase + ((size_t)i_loc*NN + j_loc)*NK),
               make_float4(e0, e1, e2, e3));
    }
}

// ---------------- launch ------------------------------------------------------
extern "C" void kernel_launch(void* const* d_in, const int* in_sizes, int n_in,
                              void* d_out, int out_size) {
    const float* x     = (const float*)d_in[0];   // (B,N,N)
    const float* ae    = (const float*)d_in[1];   // (B,N,D)
    const float* W1    = (const float*)d_in[2];   // (2D,H)
    const float* b1    = (const float*)d_in[3];   // (H)
    const float* W2    = (const float*)d_in[4];   // (H,2)
    const float* b2    = (const float*)d_in[5];   // (2)
    const float* means = (const float*)d_in[6];   // (K)
    const float* temps = (const float*)d_in[7];   // (K)
    float* out = (float*)d_out;                   // (B,N,N,K)

    dim3 gA(NB*NN/32, 8);                         // 512 blocks
    k_embed<<<gA, 128>>>(ae, W1, b1);

    dim3 gB(NN/TJQ, NN/TI, NB);                   // (8, 8, 8) = 512 blocks
    k_fused<<<gB, 256>>>(x, W2, b2, means, temps, out);
}

// round 9
// speedup vs baseline: 1.0549x; 1.0042x over previous
#include <cuda_runtime.h>

#define NB 8
#define NN 256
#define ND 128
#define NH 256
#define NK 128

typedef unsigned long long u64t;

// ---------------- scratch ----------------------------------------------------
__device__ float g_hi[NB*NN*NH];      // hi + b1 folded in   (2 MB)
__device__ float g_hj[NB*NN*NH];      // hj                  (2 MB)

// ---------------- packed f32x2 helpers ---------------------------------------
__device__ __forceinline__ u64t add2(u64t a, u64t b) {
    u64t r; asm("add.rn.f32x2 %0, %1, %2;" : "=l"(r) : "l"(a), "l"(b)); return r;
}
__device__ __forceinline__ u64t fma2(u64t a, u64t b, u64t c) {
    u64t r; asm("fma.rn.f32x2 %0, %1, %2, %3;" : "=l"(r) : "l"(a), "l"(b), "l"(c)); return r;
}
__device__ __forceinline__ u64t relu2(u64t a) {
    float lo, hi;
    asm("mov.b64 {%0,%1}, %2;" : "=f"(lo), "=f"(hi) : "l"(a));
    lo = fmaxf(lo, 0.f); hi = fmaxf(hi, 0.f);
    u64t r; asm("mov.b64 %0, {%1,%2};" : "=l"(r) : "f"(lo), "f"(hi)); return r;
}
__device__ __forceinline__ float hsum2(u64t a) {
    float lo, hi;
    asm("mov.b64 {%0,%1}, %2;" : "=f"(lo), "=f"(hi) : "l"(a));
    return lo + hi;
}
__device__ __forceinline__ float ex2a(float v) {
    float y;
    asm("ex2.approx.f32 %0, %1;" : "=f"(y) : "f"(v));
    return y;
}

// ---------------- Kernel A: [2048x128] @ [128x512] with smem-staged W1 -------
__global__ __launch_bounds__(128) void k_embed(const float* __restrict__ ae,
                                               const float* __restrict__ W1,
                                               const float* __restrict__ b1) {
    __shared__ float sa[32][129];
    __shared__ float wseg[64][64];

    int row0  = blockIdx.x * 32;
    int hcol0 = blockIdx.y * 64;
    bool isb  = hcol0 >= 256;
    int gcol  = hcol0 & 255;
    int tid   = threadIdx.x;
    int hq    = tid & 15;
    int rg    = tid >> 4;

    #pragma unroll
    for (int s = 0; s < 8; s++) {
        int idx = s*128 + tid;
        int r = idx >> 5, q = idx & 31;
        float4 v = *(const float4*)&ae[(size_t)(row0 + r)*ND + q*4];
        sa[r][q*4+0] = v.x; sa[r][q*4+1] = v.y;
        sa[r][q*4+2] = v.z; sa[r][q*4+3] = v.w;
    }

    float4 bb = isb ? make_float4(0.f,0.f,0.f,0.f)
                    : *(const float4*)&b1[gcol + hq*4];
    float4 acc0 = bb, acc1 = bb, acc2 = bb, acc3 = bb;

    const float* wbase = W1 + (size_t)(isb ? 128 : 0)*NH + gcol;

    #pragma unroll
    for (int kc = 0; kc < 128; kc += 64) {
        __syncthreads();
        #pragma unroll
        for (int s = 0; s < 8; s++) {
            int idx = s*128 + tid;
            int kk = idx >> 4, q = idx & 15;
            *(float4*)&wseg[kk][q*4] =
                *(const float4*)&wbase[(size_t)(kc + kk)*NH + q*4];
        }
        __syncthreads();

        #pragma unroll 4
        for (int kk = 0; kk < 64; kk++) {
            float4 w = *(const float4*)&wseg[kk][hq*4];
            float a0 = sa[rg*4+0][kc+kk];
            float a1 = sa[rg*4+1][kc+kk];
            float a2 = sa[rg*4+2][kc+kk];
            float a3 = sa[rg*4+3][kc+kk];
            acc0.x = fmaf(a0,w.x,acc0.x); acc0.y = fmaf(a0,w.y,acc0.y);
            acc0.z = fmaf(a0,w.z,acc0.z); acc0.w = fmaf(a0,w.w,acc0.w);
            acc1.x = fmaf(a1,w.x,acc1.x); acc1.y = fmaf(a1,w.y,acc1.y);
            acc1.z = fmaf(a1,w.z,acc1.z); acc1.w = fmaf(a1,w.w,acc1.w);
            acc2.x = fmaf(a2,w.x,acc2.x); acc2.y = fmaf(a2,w.y,acc2.y);
            acc2.z = fmaf(a2,w.z,acc2.z); acc2.w = fmaf(a2,w.w,acc2.w);
            acc3.x = fmaf(a3,w.x,acc3.x); acc3.y = fmaf(a3,w.y,acc3.y);
            acc3.z = fmaf(a3,w.z,acc3.z); acc3.w = fmaf(a3,w.w,acc3.w);
        }
    }

    float* dst = isb ? g_hj : g_hi;
    int c = (isb ? hcol0 - 256 : hcol0) + hq*4;
    int r0 = row0 + rg*4;
    *(float4*)&dst[(size_t)(r0+0)*NH + c] = acc0;
    *(float4*)&dst[(size_t)(r0+1)*NH + c] = acc1;
    *(float4*)&dst[(size_t)(r0+2)*NH + c] = acc2;
    *(float4*)&dst[(size_t)(r0+3)*NH + c] = acc3;
}

// ---------------- Kernel B: warp-autonomous fused pair-MLP + RBF -------------
// 128 threads, 32x32 tile. ONE block barrier (hj+W2 staging). Then each warp
// independently: 2 sub-rounds of [stage private 4-row hi slice -> full-K MLP
// (2x2 pairs/thread) -> v in regs -> RBF via shfl-broadcast of v -> stores].
// No smem handoff, no post-start block barriers: warps desync so MLP of some
// overlaps stores of others chip-wide.
#define TIB 32
#define TJB 32
#define PADR 260

// dynamic smem layout (floats)
#define OFF_SHJ 0
#define OFF_SHI (TJB*PADR)                  // 4 warps x 4*PADR
#define OFF_SW0 (OFF_SHI + 16*PADR)
#define OFF_SW1 (OFF_SW0 + NH)
#define SMEM_FLOATS (OFF_SW1 + NH)
#define SMEM_BYTES (SMEM_FLOATS*4)

#define PSTEP4(A0,A1,C0,C1,W0,W1v) {                                     \
    u64t r00 = relu2(add2((A0), (C0)));                                   \
    u64t r01 = relu2(add2((A0), (C1)));                                   \
    u64t r10 = relu2(add2((A1), (C0)));                                   \
    u64t r11 = relu2(add2((A1), (C1)));                                   \
    acc00a = fma2(r00, (W0), acc00a); acc00b = fma2(r00, (W1v), acc00b);  \
    acc01a = fma2(r01, (W0), acc01a); acc01b = fma2(r01, (W1v), acc01b);  \
    acc10a = fma2(r10, (W0), acc10a); acc10b = fma2(r10, (W1v), acc10b);  \
    acc11a = fma2(r11, (W0), acc11a); acc11b = fma2(r11, (W1v), acc11b); }

__global__ __launch_bounds__(128) void k_fused(
        const float* __restrict__ x,
        const float* __restrict__ W2,
        const float* __restrict__ b2,
        const float* __restrict__ means,
        const float* __restrict__ temps,
        float* __restrict__ out) {
    extern __shared__ float sm[];
    float* shj = sm + OFF_SHJ;
    float* sw0 = sm + OFF_SW0;
    float* sw1 = sm + OFF_SW1;

    int b  = blockIdx.z;
    int i0 = blockIdx.y * TIB;
    int j0 = blockIdx.x * TJB;
    int tid  = threadIdx.x;                // 0..127
    int lane = tid & 31;
    int wrp  = tid >> 5;                   // 0..3

    // stage block-shared hj tile (32x256) + W2 columns, then ONE barrier
    {
        const float* hj_base = g_hj + (size_t)(b*NN + j0)*NH;
        #pragma unroll
        for (int s = 0; s < 16; s++) {
            int idx = s*128 + tid;         // 0..2047
            int r = idx >> 6, c = idx & 63;
            *(float4*)&shj[r*PADR + c*4] =
                *(const float4*)&hj_base[(size_t)r*NH + c*4];
        }
        #pragma unroll
        for (int h = tid; h < NH; h += 128) {
            sw0[h] = W2[2*h];
            sw1[h] = W2[2*h + 1];
        }
    }
    __syncthreads();                       // the only block-wide barrier

    // per-lane RBF constants: arg = n*v^2 + p*v + q
    const float L2E = 1.4426950408889634f;
    int k0 = lane * 4;
    float4 mm4 = *(const float4*)&means[k0];
    float4 tt4 = *(const float4*)&temps[k0];
    float nA0 = -fabsf(tt4.x)*L2E, nA1 = -fabsf(tt4.y)*L2E;
    float nA2 = -fabsf(tt4.z)*L2E, nA3 = -fabsf(tt4.w)*L2E;
    float pB0 = -2.f*nA0*mm4.x, pB1 = -2.f*nA1*mm4.y;
    float pB2 = -2.f*nA2*mm4.z, pB3 = -2.f*nA3*mm4.w;
    float qC0 = nA0*mm4.x*mm4.x, qC1 = nA1*mm4.y*mm4.y;
    float qC2 = nA2*mm4.z*mm4.z, qC3 = nA3*mm4.w*mm4.w;

    const float sS = 0.0625f;              // 1/sqrt(2*128)
    float cb0 = __ldg(&b2[0]) * sS;
    float cb1 = __ldg(&b2[1]) * sS;

    int il = lane >> 4;                    // 0..1 (i sub-group)
    int jl = lane & 15;                    // j rows jl, jl+16

    float* myshi = sm + OFF_SHI + wrp*(4*PADR);

    #pragma unroll 1
    for (int sr = 0; sr < 2; sr++) {
        int base_i = wrp*8 + sr*4;
        const float* hi_rows = g_hi + (size_t)(b*NN + i0 + base_i)*NH;

        __syncwarp();                      // slice reuse: prior MLP reads done
        #pragma unroll
        for (int s = 0; s < 8; s++) {
            int idx = s*32 + lane;         // 0..255 float4
            int r = idx >> 6, c = idx & 63;
            *(float4*)&myshi[r*PADR + c*4] =
                *(const float4*)&hi_rows[(size_t)r*NH + c*4];
        }
        __syncwarp();

        // ---- MLP over full K=256 (2x2 pairs/thread) ----
        u64t acc00a=0ull, acc00b=0ull, acc01a=0ull, acc01b=0ull;
        u64t acc10a=0ull, acc10b=0ull, acc11a=0ull, acc11b=0ull;

        #pragma unroll 2
        for (int h4 = 0; h4 < NH/4; h4++) {
            ulonglong2 A0 = *(const ulonglong2*)&myshi[(2*il  )*PADR + h4*4];
            ulonglong2 A1 = *(const ulonglong2*)&myshi[(2*il+1)*PADR + h4*4];
            ulonglong2 C0 = *(const ulonglong2*)&shj[(jl   )*PADR + h4*4];
            ulonglong2 C1 = *(const ulonglong2*)&shj[(jl+16)*PADR + h4*4];
            ulonglong2 W0 = *(const ulonglong2*)&sw0[h4*4];
            ulonglong2 W1v= *(const ulonglong2*)&sw1[h4*4];
            PSTEP4(A0.x, A1.x, C0.x, C1.x, W0.x, W1v.x);
            PSTEP4(A0.y, A1.y, C0.y, C1.y, W0.y, W1v.y);
        }

        // ---- v in registers: pairs (base_i + 2*il + a, j0 + jl + 16*bj) ----
        float vv[2][2];
        {
            const float* xb = x + (size_t)(b*NN + i0 + base_i + 2*il)*NN + j0;
            float x00 = __ldg(&xb[jl]);
            float x01 = __ldg(&xb[jl + 16]);
            float x10 = __ldg(&xb[NN + jl]);
            float x11 = __ldg(&xb[NN + jl + 16]);
            float m00 = fmaf(hsum2(acc00a), sS, cb0);
            float b00 = fmaf(hsum2(acc00b), sS, cb1);
            float m01 = fmaf(hsum2(acc01a), sS, cb0);
            float b01 = fmaf(hsum2(acc01b), sS, cb1);
            float m10 = fmaf(hsum2(acc10a), sS, cb0);
            float b10 = fmaf(hsum2(acc10b), sS, cb1);
            float m11 = fmaf(hsum2(acc11a), sS, cb0);
            float b11 = fmaf(hsum2(acc11b), sS, cb1);
            vv[0][0] = fmaf(m00, x00, b00);
            vv[0][1] = fmaf(m01, x01, b01);
            vv[1][0] = fmaf(m10, x10, b10);
            vv[1][1] = fmaf(m11, x11, b11);
        }

        // ---- RBF + stores: warp covers one pair per STG.128 ----
        // pair (r, jj): owner lane = (r>>1)*16 + (jj&15), value vv[r&1][jj>>4]
        float* orow0 = out + ((size_t)((b*NN + i0 + base_i))*NN + j0)*NK + k0;
        #pragma unroll
        for (int r = 0; r < 4; r++) {
            int srcb = (r >> 1) * 16;
            float* orow = orow0 + (size_t)r*NN*NK;
            #pragma unroll 4
            for (int jj = 0; jj < 32; jj++) {
                float v = __shfl_sync(0xffffffffu, vv[r & 1][jj >> 4],
                                      srcb + (jj & 15));
                float e0 = ex2a(fmaf(fmaf(nA0, v, pB0), v, qC0));
                float e1 = ex2a(fmaf(fmaf(nA1, v, pB1), v, qC1));
                float e2 = ex2a(fmaf(fmaf(nA2, v, pB2), v, qC2));
                float e3 = ex2a(fmaf(fmaf(nA3, v, pB3), v, qC3));
                __stcs((float4*)(orow + (size_t)jj*NK),
                       make_float4(e0, e1, e2, e3));
            }
        }
    }
}

// ---------------- launch ------------------------------------------------------
extern "C" void kernel_launch(void* const* d_in, const int* in_sizes, int n_in,
                              void* d_out, int out_size) {
    const float* x     = (const float*)d_in[0];   // (B,N,N)
    const float* ae    = (const float*)d_in[1];   // (B,N,D)
    const float* W1    = (const float*)d_in[2];   // (2D,H)
    const float* b1    = (const float*)d_in[3];   // (H)
    const float* W2    = (const float*)d_in[4];   // (H,2)
    const float* b2    = (const float*)d_in[5];   // (2)
    const float* means = (const float*)d_in[6];   // (K)
    const float* temps = (const float*)d_in[7];   // (K)
    float* out = (float*)d_out;                   // (B,N,N,K)

    dim3 gA(NB*NN/32, 8);                         // 512 blocks
    k_embed<<<gA, 128>>>(ae, W1, b1);

    cudaFuncSetAttribute(k_fused, cudaFuncAttributeMaxDynamicSharedMemorySize,
                         SMEM_BYTES);
    dim3 gB(NN/TJB, NN/TIB, NB);                  // (8, 8, 8) = 512 blocks
    k_fused<<<gB, 128, SMEM_BYTES>>>(x, W2, b2, means, temps, out);
}